// round 10
// baseline (speedup 1.0000x reference)
#include <cuda_runtime.h>
#include <cstdint>

#define NPTS 1024
#define WEIGHT_THRESH 0.5f
#define EPS_W 1e-5f
#define RED_BLOCKS 444          // 3 resident blocks per SM on 148 SMs
#define MAX_ITERS 16            // >= ceil(4096/444) = 10

#define SRC_BYTES (NPTS * 3 * 4)            // 12288 per batch (src or tgt)
#define W_BYTES   (NPTS * 4)                //  4096 per batch
#define STAGE_BYTES (2 * SRC_BYTES + W_BYTES)  // 28672
// dynamic smem layout
#define OFF_STAGE0  0
#define OFF_STAGE1  STAGE_BYTES
#define OFF_MBAR    (2 * STAGE_BYTES)               // 2 x 8B mbarriers
#define OFF_SCRATCH (OFF_MBAR + 16)                 // 2 x 8 x 16 floats = 1024B
#define OFF_SVD     (OFF_SCRATCH + 1024)            // MAX_ITERS x 16 floats
#define SMEM_TOTAL  (OFF_SVD + MAX_ITERS * 16 * 4)  // 59408 B

__device__ __forceinline__ uint32_t smem_u32(const void* p) {
    uint32_t a;
    asm("{ .reg .u64 t; cvta.to.shared.u64 t, %1; cvt.u32.u64 %0, t; }"
        : "=r"(a) : "l"(p));
    return a;
}

__device__ __forceinline__ void bulk_copy(uint32_t dst_smem, const void* gsrc,
                                          uint32_t bytes, uint32_t mbar) {
    asm volatile(
        "cp.async.bulk.shared::cluster.global.mbarrier::complete_tx::bytes "
        "[%0], [%1], %2, [%3];"
        :: "r"(dst_smem), "l"(gsrc), "r"(bytes), "r"(mbar) : "memory");
}

__device__ __forceinline__ void mbar_wait(uint32_t mbar, int phase) {
    uint32_t done;
    do {
        asm volatile(
            "{ .reg .pred p; "
            "mbarrier.try_wait.parity.acquire.cta.shared::cta.b64 p, [%1], %2, 0x989680; "
            "selp.b32 %0, 1, 0, p; }"
            : "=r"(done) : "r"(mbar), "r"((uint32_t)phase) : "memory");
    } while (!done);
}

// ---------------------------------------------------------------------------
// Fused persistent kernel: TMA bulk-copy batch staging into double-buffered
// smem, conflict-free LDS consumption, reduce-scatter butterfly, per-block
// SIMT SVD tail.
// ---------------------------------------------------------------------------
__global__ __launch_bounds__(256, 3)
void wproc_fused(const float* __restrict__ src,
                 const float* __restrict__ tgt,
                 const float* __restrict__ wgt,
                 float* __restrict__ Rout,
                 float* __restrict__ tout,
                 int B)
{
    extern __shared__ char smem[];
    const uint32_t smem_base = smem_u32(smem);
    const int tid    = threadIdx.x;
    const int stride = gridDim.x;
    const int warp   = tid >> 5, lane = tid & 31;

    float* scratch = (float*)(smem + OFF_SCRATCH);   // [2][8][16]
    float* svd_sm  = (float*)(smem + OFF_SVD);       // [MAX_ITERS][16]

    if (tid == 0) {
        asm volatile("mbarrier.init.shared::cta.b64 [%0], 1;"
                     :: "r"(smem_base + OFF_MBAR) : "memory");
        asm volatile("mbarrier.init.shared::cta.b64 [%0], 1;"
                     :: "r"(smem_base + OFF_MBAR + 8) : "memory");
        asm volatile("fence.proxy.async.shared::cta;" ::: "memory");
    }
    __syncthreads();

    int b  = blockIdx.x;     // grid is clamped to <= B, so b < B always
    int it = 0;
    int p  = 0;
    int ph0 = 0, ph1 = 0;

    // Prologue: issue copies for first batch into stage 0
    if (tid == 0) {
        uint32_t mb  = smem_base + OFF_MBAR;
        uint32_t dst = smem_base + OFF_STAGE0;
        asm volatile("mbarrier.arrive.expect_tx.shared::cta.b64 _, [%0], %1;"
                     :: "r"(mb), "r"((uint32_t)STAGE_BYTES) : "memory");
        bulk_copy(dst,             (const char*)src + (size_t)b * SRC_BYTES, SRC_BYTES, mb);
        bulk_copy(dst + SRC_BYTES, (const char*)tgt + (size_t)b * SRC_BYTES, SRC_BYTES, mb);
        bulk_copy(dst + 2*SRC_BYTES,(const char*)wgt + (size_t)b * W_BYTES,  W_BYTES,  mb);
    }

    while (true) {
        const int bn = b + stride;
        const bool has_next = (bn < B);

        // Issue copies for next batch into the other stage (it was fully
        // consumed before the previous iteration's barrier).
        if (tid == 0 && has_next) {
            uint32_t mb  = smem_base + OFF_MBAR + ((p ^ 1) << 3);
            uint32_t dst = smem_base + (p ? OFF_STAGE0 : OFF_STAGE1);
            asm volatile("mbarrier.arrive.expect_tx.shared::cta.b64 _, [%0], %1;"
                         :: "r"(mb), "r"((uint32_t)STAGE_BYTES) : "memory");
            bulk_copy(dst,              (const char*)src + (size_t)bn * SRC_BYTES, SRC_BYTES, mb);
            bulk_copy(dst + SRC_BYTES,  (const char*)tgt + (size_t)bn * SRC_BYTES, SRC_BYTES, mb);
            bulk_copy(dst + 2*SRC_BYTES,(const char*)wgt + (size_t)bn * W_BYTES,   W_BYTES,  mb);
        }

        // Wait for current stage's data
        {
            uint32_t mb = smem_base + OFF_MBAR + (p << 3);
            int phase = p ? ph1 : ph0;
            mbar_wait(mb, phase);
            if (p) ph1 ^= 1; else ph0 ^= 1;
        }

        // ---- consume stage p from smem (conflict-free LDS) ----
        const char* st = smem + (p ? OFF_STAGE1 : OFF_STAGE0);
        const float4* s4 = (const float4*)(st);
        const float4* t4 = (const float4*)(st + SRC_BYTES);
        const float4* w4 = (const float4*)(st + 2 * SRC_BYTES);

        float4 wv = w4[tid];
        float4 a0 = s4[3 * tid + 0];
        float4 a1 = s4[3 * tid + 1];
        float4 a2 = s4[3 * tid + 2];
        float4 c0 = t4[3 * tid + 0];
        float4 c1 = t4[3 * tid + 1];
        float4 c2 = t4[3 * tid + 2];

        float ws[4];
        ws[0] = (wv.x < WEIGHT_THRESH) ? 0.0f : wv.x;
        ws[1] = (wv.y < WEIGHT_THRESH) ? 0.0f : wv.y;
        ws[2] = (wv.z < WEIGHT_THRESH) ? 0.0f : wv.z;
        ws[3] = (wv.w < WEIGHT_THRESH) ? 0.0f : wv.w;

        float px[4][3] = {{a0.x, a0.y, a0.z},
                          {a0.w, a1.x, a1.y},
                          {a1.z, a1.w, a2.x},
                          {a2.y, a2.z, a2.w}};
        float py[4][3] = {{c0.x, c0.y, c0.z},
                          {c0.w, c1.x, c1.y},
                          {c1.z, c1.w, c2.x},
                          {c2.y, c2.z, c2.w}};

        float acc[16];
        #pragma unroll
        for (int k = 0; k < 16; k++) acc[k] = 0.0f;

        #pragma unroll
        for (int k = 0; k < 4; k++) {
            float w = ws[k];
            float x0 = px[k][0], x1 = px[k][1], x2 = px[k][2];
            float y0 = py[k][0], y1 = py[k][1], y2 = py[k][2];
            acc[0] += w;
            acc[1] += w * x0;  acc[2] += w * x1;  acc[3] += w * x2;
            float wy0 = w * y0, wy1 = w * y1, wy2 = w * y2;
            acc[4] += wy0;     acc[5] += wy1;     acc[6] += wy2;
            acc[7]  += x0 * wy0;  acc[8]  += x0 * wy1;  acc[9]  += x0 * wy2;
            acc[10] += x1 * wy0;  acc[11] += x1 * wy1;  acc[12] += x1 * wy2;
            acc[13] += x2 * wy0;  acc[14] += x2 * wy1;  acc[15] += x2 * wy2;
        }

        // ---- reduce-scatter butterfly ----
        {
            bool hi = (lane & 16) != 0;
            #pragma unroll
            for (int j = 0; j < 8; j++) {
                float send = hi ? acc[j] : acc[j + 8];
                float keep = hi ? acc[j + 8] : acc[j];
                acc[j] = keep + __shfl_xor_sync(0xffffffffu, send, 16);
            }
        }
        {
            bool hi = (lane & 8) != 0;
            #pragma unroll
            for (int j = 0; j < 4; j++) {
                float send = hi ? acc[j] : acc[j + 4];
                float keep = hi ? acc[j + 4] : acc[j];
                acc[j] = keep + __shfl_xor_sync(0xffffffffu, send, 8);
            }
        }
        {
            bool hi = (lane & 4) != 0;
            #pragma unroll
            for (int j = 0; j < 2; j++) {
                float send = hi ? acc[j] : acc[j + 2];
                float keep = hi ? acc[j + 2] : acc[j];
                acc[j] = keep + __shfl_xor_sync(0xffffffffu, send, 4);
            }
        }
        {
            bool hi = (lane & 2) != 0;
            float send = hi ? acc[0] : acc[1];
            float keep = hi ? acc[1] : acc[0];
            acc[0] = keep + __shfl_xor_sync(0xffffffffu, send, 2);
        }
        acc[0] += __shfl_xor_sync(0xffffffffu, acc[0], 1);

        const int accIdx = (lane >> 1) & 15;
        if ((lane & 1) == 0)
            scratch[(it & 1) * 128 + warp * 16 + accIdx] = acc[0];
        __syncthreads();   // stage p fully read + scratch visible
        if (tid < 16) {
            float s = 0.0f;
            #pragma unroll
            for (int w = 0; w < 8; w++)
                s += scratch[(it & 1) * 128 + w * 16 + tid];
            svd_sm[it * 16 + tid] = s;
        }

        if (!has_next) break;
        b = bn; p ^= 1; it++;
    }

    // ---------------- SVD tail: warp-0 lanes, one batch each ---------------
    __syncthreads();

    const int niter = (B - blockIdx.x + stride - 1) / stride;
    if (tid >= niter) return;

    const int myb = blockIdx.x + tid * stride;

    float tot[16];
    #pragma unroll
    for (int k = 0; k < 16; k++) tot[k] = svd_sm[tid * 16 + k];

    float W  = tot[0];
    float d  = W + EPS_W;
    float id = __fdividef(1.0f, d);
    float coef = (2.0f * d - W) * id * id * id;

    float Sx[3] = {tot[1], tot[2], tot[3]};
    float Sy[3] = {tot[4], tot[5], tot[6]};
    float H[3][3];
    #pragma unroll
    for (int i = 0; i < 3; i++)
        #pragma unroll
        for (int j = 0; j < 3; j++)
            H[i][j] = tot[7 + i * 3 + j] * id - Sx[i] * Sy[j] * coef;

    float src_c[3] = {Sx[0] * id, Sx[1] * id, Sx[2] * id};
    float tgt_c[3] = {Sy[0] * id, Sy[1] * id, Sy[2] * id};

    float A[3][3];
    #pragma unroll
    for (int i = 0; i < 3; i++)
        #pragma unroll
        for (int j = 0; j < 3; j++) {
            float s = 0.0f;
            #pragma unroll
            for (int k = 0; k < 3; k++) s += H[k][i] * H[k][j];
            A[i][j] = s;
        }

    float V[3][3] = {{1, 0, 0}, {0, 1, 0}, {0, 0, 1}};

    #pragma unroll 1
    for (int sweep = 0; sweep < 4; sweep++) {
        #pragma unroll
        for (int pair = 0; pair < 3; pair++) {
            const int p2 = (pair == 2) ? 1 : 0;
            const int q2 = (pair == 0) ? 1 : 2;
            float apq = A[p2][q2];
            if (fabsf(apq) > 1e-30f) {
                float tau = __fdividef(A[q2][q2] - A[p2][p2], 2.0f * apq);
                tau = fminf(fmaxf(tau, -1e18f), 1e18f);   // overflow-safe
                float h   = 1.0f + tau * tau;
                float sq  = h * rsqrtf(h);                // sqrt(1+tau^2)
                float tt  = __fdividef(copysignf(1.0f, tau),
                                       fabsf(tau) + sq);
                float cc  = rsqrtf(1.0f + tt * tt);
                float ss  = tt * cc;
                #pragma unroll
                for (int k = 0; k < 3; k++) {
                    float akp = A[k][p2], akq = A[k][q2];
                    A[k][p2] = cc * akp - ss * akq;
                    A[k][q2] = ss * akp + cc * akq;
                }
                #pragma unroll
                for (int k = 0; k < 3; k++) {
                    float apk = A[p2][k], aqk = A[q2][k];
                    A[p2][k] = cc * apk - ss * aqk;
                    A[q2][k] = ss * apk + cc * aqk;
                }
                #pragma unroll
                for (int k = 0; k < 3; k++) {
                    float vkp = V[k][p2], vkq = V[k][q2];
                    V[k][p2] = cc * vkp - ss * vkq;
                    V[k][q2] = ss * vkp + cc * vkq;
                }
            }
        }
    }

    float eig[3] = {A[0][0], A[1][1], A[2][2]};
    int i0 = 0, i1 = 1, i2 = 2, tmpi;
    if (eig[i0] < eig[i1]) { tmpi = i0; i0 = i1; i1 = tmpi; }
    if (eig[i0] < eig[i2]) { tmpi = i0; i0 = i2; i2 = tmpi; }
    if (eig[i1] < eig[i2]) { tmpi = i1; i1 = i2; i2 = tmpi; }

    float v0[3] = {V[0][i0], V[1][i0], V[2][i0]};
    float v1[3] = {V[0][i1], V[1][i1], V[2][i1]};
    float v2[3] = {v0[1] * v1[2] - v0[2] * v1[1],
                   v0[2] * v1[0] - v0[0] * v1[2],
                   v0[0] * v1[1] - v0[1] * v1[0]};

    float u0[3], u1[3], u2[3];
    #pragma unroll
    for (int i = 0; i < 3; i++)
        u0[i] = H[i][0] * v0[0] + H[i][1] * v0[1] + H[i][2] * v0[2];
    float rn0 = rsqrtf(u0[0] * u0[0] + u0[1] * u0[1] + u0[2] * u0[2] + 1e-30f);
    u0[0] *= rn0; u0[1] *= rn0; u0[2] *= rn0;

    #pragma unroll
    for (int i = 0; i < 3; i++)
        u1[i] = H[i][0] * v1[0] + H[i][1] * v1[1] + H[i][2] * v1[2];
    float dp = u1[0] * u0[0] + u1[1] * u0[1] + u1[2] * u0[2];
    u1[0] -= dp * u0[0]; u1[1] -= dp * u0[1]; u1[2] -= dp * u0[2];
    float rn1 = rsqrtf(u1[0] * u1[0] + u1[1] * u1[1] + u1[2] * u1[2] + 1e-30f);
    u1[0] *= rn1; u1[1] *= rn1; u1[2] *= rn1;

    u2[0] = u0[1] * u1[2] - u0[2] * u1[1];
    u2[1] = u0[2] * u1[0] - u0[0] * u1[2];
    u2[2] = u0[0] * u1[1] - u0[1] * u1[0];

    float R[3][3];
    #pragma unroll
    for (int i = 0; i < 3; i++)
        #pragma unroll
        for (int j = 0; j < 3; j++)
            R[i][j] = v0[i] * u0[j] + v1[i] * u1[j] + v2[i] * u2[j];

    float t[3];
    #pragma unroll
    for (int i = 0; i < 3; i++)
        t[i] = tgt_c[i] - (R[i][0] * src_c[0] + R[i][1] * src_c[1] + R[i][2] * src_c[2]);

    float* Rb = Rout + (size_t)myb * 9;
    #pragma unroll
    for (int i = 0; i < 3; i++)
        #pragma unroll
        for (int j = 0; j < 3; j++)
            Rb[i * 3 + j] = R[i][j];
    float* tb = tout + (size_t)myb * 3;
    tb[0] = t[0]; tb[1] = t[1]; tb[2] = t[2];
}

extern "C" void kernel_launch(void* const* d_in, const int* in_sizes, int n_in,
                              void* d_out, int out_size)
{
    const float* src = (const float*)d_in[0];
    const float* tgt = (const float*)d_in[1];
    const float* w   = (const float*)d_in[2];
    int B = in_sizes[2] / NPTS;
    float* Rout = (float*)d_out;
    float* tout = Rout + (size_t)B * 9;

    cudaFuncSetAttribute(wproc_fused,
                         cudaFuncAttributeMaxDynamicSharedMemorySize, SMEM_TOTAL);
    int grid = (B < RED_BLOCKS) ? B : RED_BLOCKS;
    wproc_fused<<<grid, 256, SMEM_TOTAL>>>(src, tgt, w, Rout, tout, B);
}

// round 11
// speedup vs baseline: 1.0102x; 1.0102x over previous
#include <cuda_runtime.h>
#include <cstdint>

#define NPTS 1024
#define WEIGHT_THRESH 0.5f
#define EPS_W 1e-5f
#define RED_BLOCKS 296          // 2 resident blocks per SM on 148 SMs
#define MAX_ITERS 16            // >= ceil(4096/296) = 14
#define N_STAGES 3

#define SRC_BYTES (NPTS * 3 * 4)               // 12288 per batch (src or tgt)
#define W_BYTES   (NPTS * 4)                   //  4096 per batch
#define STAGE_BYTES (2 * SRC_BYTES + W_BYTES)  // 28672
// dynamic smem layout
#define OFF_STAGES  0
#define OFF_MBAR    (N_STAGES * STAGE_BYTES)           // 3 x 8B mbarriers
#define OFF_SCRATCH (OFF_MBAR + 32)                    // 2 x 8 x 16 floats
#define OFF_SVD     (OFF_SCRATCH + 1024)               // MAX_ITERS x 16 floats
#define SMEM_TOTAL  (OFF_SVD + MAX_ITERS * 16 * 4)     // ~88 KB

__device__ __forceinline__ uint32_t smem_u32(const void* p) {
    uint32_t a;
    asm("{ .reg .u64 t; cvta.to.shared.u64 t, %1; cvt.u32.u64 %0, t; }"
        : "=r"(a) : "l"(p));
    return a;
}

__device__ __forceinline__ void bulk_copy(uint32_t dst_smem, const void* gsrc,
                                          uint32_t bytes, uint32_t mbar) {
    asm volatile(
        "cp.async.bulk.shared::cluster.global.mbarrier::complete_tx::bytes "
        "[%0], [%1], %2, [%3];"
        :: "r"(dst_smem), "l"(gsrc), "r"(bytes), "r"(mbar) : "memory");
}

__device__ __forceinline__ void mbar_wait(uint32_t mbar, int phase) {
    uint32_t done;
    do {
        asm volatile(
            "{ .reg .pred p; "
            "mbarrier.try_wait.parity.acquire.cta.shared::cta.b64 p, [%1], %2, 0x989680; "
            "selp.b32 %0, 1, 0, p; }"
            : "=r"(done) : "r"(mbar), "r"((uint32_t)phase) : "memory");
    } while (!done);
}

// ---------------------------------------------------------------------------
// Fused persistent kernel: 3-stage TMA bulk-copy ring (2 fetches always in
// flight), conflict-free LDS consumption, reduce-scatter butterfly, SIMT SVD
// tail.
// ---------------------------------------------------------------------------
__global__ __launch_bounds__(256, 2)
void wproc_fused(const float* __restrict__ src,
                 const float* __restrict__ tgt,
                 const float* __restrict__ wgt,
                 float* __restrict__ Rout,
                 float* __restrict__ tout,
                 int B)
{
    extern __shared__ char smem[];
    const uint32_t smem_base = smem_u32(smem);
    const int tid    = threadIdx.x;
    const int stride = gridDim.x;
    const int warp   = tid >> 5, lane = tid & 31;
    const int b0     = blockIdx.x;     // grid clamped to <= B

    float* scratch = (float*)(smem + OFF_SCRATCH);   // [2][8][16]
    float* svd_sm  = (float*)(smem + OFF_SVD);       // [MAX_ITERS][16]

    if (tid == 0) {
        #pragma unroll
        for (int s = 0; s < N_STAGES; s++)
            asm volatile("mbarrier.init.shared::cta.b64 [%0], 1;"
                         :: "r"(smem_base + OFF_MBAR + s * 8) : "memory");
        asm volatile("fence.proxy.async.shared::cta;" ::: "memory");
    }
    __syncthreads();

    // issue(j): fetch batch b0 + j*stride into stage j%3
    auto issue = [&](int j) {
        const int bj = b0 + j * stride;
        uint32_t mb  = smem_base + OFF_MBAR + (j % N_STAGES) * 8;
        uint32_t dst = smem_base + OFF_STAGES + (j % N_STAGES) * STAGE_BYTES;
        asm volatile("mbarrier.arrive.expect_tx.shared::cta.b64 _, [%0], %1;"
                     :: "r"(mb), "r"((uint32_t)STAGE_BYTES) : "memory");
        bulk_copy(dst,               (const char*)src + (size_t)bj * SRC_BYTES, SRC_BYTES, mb);
        bulk_copy(dst + SRC_BYTES,   (const char*)tgt + (size_t)bj * SRC_BYTES, SRC_BYTES, mb);
        bulk_copy(dst + 2*SRC_BYTES, (const char*)wgt + (size_t)bj * W_BYTES,   W_BYTES,  mb);
    };

    // Prologue: two fetches in flight
    if (tid == 0) {
        issue(0);
        if (b0 + stride < B) issue(1);
    }

    for (int it = 0; ; it++) {
        // Keep two ahead: issue it+2 (its buffer was retired at end of it-1)
        if (tid == 0 && b0 + (it + 2) * stride < B) issue(it + 2);

        // Wait for current stage
        mbar_wait(smem_base + OFF_MBAR + (it % N_STAGES) * 8,
                  (it / N_STAGES) & 1);

        // ---- consume stage from smem (conflict-free LDS) ----
        const char* st = smem + OFF_STAGES + (it % N_STAGES) * STAGE_BYTES;
        const float4* s4 = (const float4*)(st);
        const float4* t4 = (const float4*)(st + SRC_BYTES);
        const float4* w4 = (const float4*)(st + 2 * SRC_BYTES);

        float4 wv = w4[tid];
        float4 a0 = s4[3 * tid + 0];
        float4 a1 = s4[3 * tid + 1];
        float4 a2 = s4[3 * tid + 2];
        float4 c0 = t4[3 * tid + 0];
        float4 c1 = t4[3 * tid + 1];
        float4 c2 = t4[3 * tid + 2];

        float ws[4];
        ws[0] = (wv.x < WEIGHT_THRESH) ? 0.0f : wv.x;
        ws[1] = (wv.y < WEIGHT_THRESH) ? 0.0f : wv.y;
        ws[2] = (wv.z < WEIGHT_THRESH) ? 0.0f : wv.z;
        ws[3] = (wv.w < WEIGHT_THRESH) ? 0.0f : wv.w;

        float px[4][3] = {{a0.x, a0.y, a0.z},
                          {a0.w, a1.x, a1.y},
                          {a1.z, a1.w, a2.x},
                          {a2.y, a2.z, a2.w}};
        float py[4][3] = {{c0.x, c0.y, c0.z},
                          {c0.w, c1.x, c1.y},
                          {c1.z, c1.w, c2.x},
                          {c2.y, c2.z, c2.w}};

        float acc[16];
        #pragma unroll
        for (int k = 0; k < 16; k++) acc[k] = 0.0f;

        #pragma unroll
        for (int k = 0; k < 4; k++) {
            float w = ws[k];
            float x0 = px[k][0], x1 = px[k][1], x2 = px[k][2];
            float y0 = py[k][0], y1 = py[k][1], y2 = py[k][2];
            acc[0] += w;
            acc[1] += w * x0;  acc[2] += w * x1;  acc[3] += w * x2;
            float wy0 = w * y0, wy1 = w * y1, wy2 = w * y2;
            acc[4] += wy0;     acc[5] += wy1;     acc[6] += wy2;
            acc[7]  += x0 * wy0;  acc[8]  += x0 * wy1;  acc[9]  += x0 * wy2;
            acc[10] += x1 * wy0;  acc[11] += x1 * wy1;  acc[12] += x1 * wy2;
            acc[13] += x2 * wy0;  acc[14] += x2 * wy1;  acc[15] += x2 * wy2;
        }

        // ---- reduce-scatter butterfly ----
        {
            bool hi = (lane & 16) != 0;
            #pragma unroll
            for (int j = 0; j < 8; j++) {
                float send = hi ? acc[j] : acc[j + 8];
                float keep = hi ? acc[j + 8] : acc[j];
                acc[j] = keep + __shfl_xor_sync(0xffffffffu, send, 16);
            }
        }
        {
            bool hi = (lane & 8) != 0;
            #pragma unroll
            for (int j = 0; j < 4; j++) {
                float send = hi ? acc[j] : acc[j + 4];
                float keep = hi ? acc[j + 4] : acc[j];
                acc[j] = keep + __shfl_xor_sync(0xffffffffu, send, 8);
            }
        }
        {
            bool hi = (lane & 4) != 0;
            #pragma unroll
            for (int j = 0; j < 2; j++) {
                float send = hi ? acc[j] : acc[j + 2];
                float keep = hi ? acc[j + 2] : acc[j];
                acc[j] = keep + __shfl_xor_sync(0xffffffffu, send, 4);
            }
        }
        {
            bool hi = (lane & 2) != 0;
            float send = hi ? acc[0] : acc[1];
            float keep = hi ? acc[1] : acc[0];
            acc[0] = keep + __shfl_xor_sync(0xffffffffu, send, 2);
        }
        acc[0] += __shfl_xor_sync(0xffffffffu, acc[0], 1);

        const int accIdx = (lane >> 1) & 15;
        if ((lane & 1) == 0)
            scratch[(it & 1) * 128 + warp * 16 + accIdx] = acc[0];
        __syncthreads();   // retires this stage buffer + scratch visible
        if (tid < 16) {
            float s = 0.0f;
            #pragma unroll
            for (int w = 0; w < 8; w++)
                s += scratch[(it & 1) * 128 + w * 16 + tid];
            svd_sm[it * 16 + tid] = s;
        }

        if (b0 + (it + 1) * stride >= B) break;
    }

    // ---------------- SVD tail: warp-0 lanes, one batch each ---------------
    __syncthreads();

    const int niter = (B - b0 + stride - 1) / stride;
    if (tid >= niter) return;

    const int myb = b0 + tid * stride;

    float tot[16];
    #pragma unroll
    for (int k = 0; k < 16; k++) tot[k] = svd_sm[tid * 16 + k];

    float W  = tot[0];
    float d  = W + EPS_W;
    float id = __fdividef(1.0f, d);
    float coef = (2.0f * d - W) * id * id * id;

    float Sx[3] = {tot[1], tot[2], tot[3]};
    float Sy[3] = {tot[4], tot[5], tot[6]};
    float H[3][3];
    #pragma unroll
    for (int i = 0; i < 3; i++)
        #pragma unroll
        for (int j = 0; j < 3; j++)
            H[i][j] = tot[7 + i * 3 + j] * id - Sx[i] * Sy[j] * coef;

    float src_c[3] = {Sx[0] * id, Sx[1] * id, Sx[2] * id};
    float tgt_c[3] = {Sy[0] * id, Sy[1] * id, Sy[2] * id};

    float A[3][3];
    #pragma unroll
    for (int i = 0; i < 3; i++)
        #pragma unroll
        for (int j = 0; j < 3; j++) {
            float s = 0.0f;
            #pragma unroll
            for (int k = 0; k < 3; k++) s += H[k][i] * H[k][j];
            A[i][j] = s;
        }

    float V[3][3] = {{1, 0, 0}, {0, 1, 0}, {0, 0, 1}};

    #pragma unroll 1
    for (int sweep = 0; sweep < 4; sweep++) {
        #pragma unroll
        for (int pair = 0; pair < 3; pair++) {
            const int p2 = (pair == 2) ? 1 : 0;
            const int q2 = (pair == 0) ? 1 : 2;
            float apq = A[p2][q2];
            if (fabsf(apq) > 1e-30f) {
                float tau = __fdividef(A[q2][q2] - A[p2][p2], 2.0f * apq);
                tau = fminf(fmaxf(tau, -1e18f), 1e18f);   // overflow-safe
                float h   = 1.0f + tau * tau;
                float sq  = h * rsqrtf(h);                // sqrt(1+tau^2)
                float tt  = __fdividef(copysignf(1.0f, tau),
                                       fabsf(tau) + sq);
                float cc  = rsqrtf(1.0f + tt * tt);
                float ss  = tt * cc;
                #pragma unroll
                for (int k = 0; k < 3; k++) {
                    float akp = A[k][p2], akq = A[k][q2];
                    A[k][p2] = cc * akp - ss * akq;
                    A[k][q2] = ss * akp + cc * akq;
                }
                #pragma unroll
                for (int k = 0; k < 3; k++) {
                    float apk = A[p2][k], aqk = A[q2][k];
                    A[p2][k] = cc * apk - ss * aqk;
                    A[q2][k] = ss * apk + cc * aqk;
                }
                #pragma unroll
                for (int k = 0; k < 3; k++) {
                    float vkp = V[k][p2], vkq = V[k][q2];
                    V[k][p2] = cc * vkp - ss * vkq;
                    V[k][q2] = ss * vkp + cc * vkq;
                }
            }
        }
    }

    float eig[3] = {A[0][0], A[1][1], A[2][2]};
    int i0 = 0, i1 = 1, i2 = 2, tmpi;
    if (eig[i0] < eig[i1]) { tmpi = i0; i0 = i1; i1 = tmpi; }
    if (eig[i0] < eig[i2]) { tmpi = i0; i0 = i2; i2 = tmpi; }
    if (eig[i1] < eig[i2]) { tmpi = i1; i1 = i2; i2 = tmpi; }

    float v0[3] = {V[0][i0], V[1][i0], V[2][i0]};
    float v1[3] = {V[0][i1], V[1][i1], V[2][i1]};
    float v2[3] = {v0[1] * v1[2] - v0[2] * v1[1],
                   v0[2] * v1[0] - v0[0] * v1[2],
                   v0[0] * v1[1] - v0[1] * v1[0]};

    float u0[3], u1[3], u2[3];
    #pragma unroll
    for (int i = 0; i < 3; i++)
        u0[i] = H[i][0] * v0[0] + H[i][1] * v0[1] + H[i][2] * v0[2];
    float rn0 = rsqrtf(u0[0] * u0[0] + u0[1] * u0[1] + u0[2] * u0[2] + 1e-30f);
    u0[0] *= rn0; u0[1] *= rn0; u0[2] *= rn0;

    #pragma unroll
    for (int i = 0; i < 3; i++)
        u1[i] = H[i][0] * v1[0] + H[i][1] * v1[1] + H[i][2] * v1[2];
    float dp = u1[0] * u0[0] + u1[1] * u0[1] + u1[2] * u0[2];
    u1[0] -= dp * u0[0]; u1[1] -= dp * u0[1]; u1[2] -= dp * u0[2];
    float rn1 = rsqrtf(u1[0] * u1[0] + u1[1] * u1[1] + u1[2] * u1[2] + 1e-30f);
    u1[0] *= rn1; u1[1] *= rn1; u1[2] *= rn1;

    u2[0] = u0[1] * u1[2] - u0[2] * u1[1];
    u2[1] = u0[2] * u1[0] - u0[0] * u1[2];
    u2[2] = u0[0] * u1[1] - u0[1] * u1[0];

    float R[3][3];
    #pragma unroll
    for (int i = 0; i < 3; i++)
        #pragma unroll
        for (int j = 0; j < 3; j++)
            R[i][j] = v0[i] * u0[j] + v1[i] * u1[j] + v2[i] * u2[j];

    float t[3];
    #pragma unroll
    for (int i = 0; i < 3; i++)
        t[i] = tgt_c[i] - (R[i][0] * src_c[0] + R[i][1] * src_c[1] + R[i][2] * src_c[2]);

    float* Rb = Rout + (size_t)myb * 9;
    #pragma unroll
    for (int i = 0; i < 3; i++)
        #pragma unroll
        for (int j = 0; j < 3; j++)
            Rb[i * 3 + j] = R[i][j];
    float* tb = tout + (size_t)myb * 3;
    tb[0] = t[0]; tb[1] = t[1]; tb[2] = t[2];
}

extern "C" void kernel_launch(void* const* d_in, const int* in_sizes, int n_in,
                              void* d_out, int out_size)
{
    const float* src = (const float*)d_in[0];
    const float* tgt = (const float*)d_in[1];
    const float* w   = (const float*)d_in[2];
    int B = in_sizes[2] / NPTS;
    float* Rout = (float*)d_out;
    float* tout = Rout + (size_t)B * 9;

    cudaFuncSetAttribute(wproc_fused,
                         cudaFuncAttributeMaxDynamicSharedMemorySize, SMEM_TOTAL);
    int grid = (B < RED_BLOCKS) ? B : RED_BLOCKS;
    wproc_fused<<<grid, 256, SMEM_TOTAL>>>(src, tgt, w, Rout, tout, B);
}